// round 1
// baseline (speedup 1.0000x reference)
#include <cuda_runtime.h>
#include <math.h>

// Problem constants
#define NB   64     // batch
#define NL   32     // caption length
#define NT   31     // decode steps = L-1
#define NV   16000  // vocab
#define NE   512    // ENC = DEC = ATT
#define NEMB 256
#define NP   256    // pixels
#define KS   4      // split-K factor for small-M step GEMMs

// ---------------- device scratch (no allocation allowed) ----------------
__device__ float g_enc [NB * NP * NE];        // [B][P][C]
__device__ float g_att1[NB * NP * NE];        // [B][P][A]
__device__ float g_mean[NB * NE];
__device__ float g_h   [NB * NE];
__device__ float g_c   [NB * NE];
__device__ float g_Hall[NT * NB * NE];        // h2 per step
__device__ float g_xprj[NT * NB * 2048];      // emb part of gates + b_ih + b_hh
__device__ float g_ybuf[KS * NB * 3072];      // partials of h @ [Wdec; Wbeta; Whh]
__device__ float g_gbuf[KS * NB * 2048];      // partials of awe @ W_ih[:,256:]
__device__ float g_awe [NB * NE];
__device__ float g_Wcat[3072 * 512];          // stacked [Wdec; Wbeta; Whh]
__device__ float g_bsum[2048];                // b_ih + b_hh
__device__ int   g_capx[2048];                // emb row per (t,b)
__device__ int   g_rowA[2048];                // active row -> t*64+b (into Hall)
__device__ int   g_rowO[2048];                // active row -> b*31+t (into out)
__device__ int   g_nact[1];

__device__ __forceinline__ float sigf(float x) { return 1.0f / (1.0f + expf(-x)); }

// ---------------- generic tiled SGEMM: C[M,N] = A[M,K] * B[N,K]^T (+bias) --
// A rows optionally gathered via arow[]; C rows optionally scattered via crow[].
// Split-K: gridDim.z blocks each do kchunk of K starting at z*kchunk, writing
// to C + z*czstride (bias must be null in that mode; consumer sums partials).
__global__ void sgemm64(const float* __restrict__ A, int lda, const int* __restrict__ arow,
                        const float* __restrict__ B, int ldb,
                        const float* __restrict__ bias,
                        float* __restrict__ C, int ldc, const int* __restrict__ crow,
                        int M, const int* __restrict__ Mdev,
                        int kchunk, long long czstride)
{
    int Mv = Mdev ? *Mdev : M;
    int m0 = blockIdx.x * 64;
    if (m0 >= Mv) return;
    int n0 = blockIdx.y * 64;
    int k0 = blockIdx.z * kchunk;
    C += (long long)blockIdx.z * czstride;

    __shared__ float As[16][68];
    __shared__ float Bs[16][68];

    int tid = threadIdx.x;        // 256 threads
    int tx = tid & 15;            // col group
    int ty = tid >> 4;            // row group
    int lm = tid >> 2;            // 0..63: tile row/col for loading
    int lk = (tid & 3) * 4;       // 0,4,8,12

    int rowm = m0 + lm;
    int ca   = (rowm < Mv) ? rowm : (Mv - 1);
    int ar   = arow ? arow[ca] : ca;
    const float* Arow = A + (long long)ar * lda + k0;
    const float* Brow = B + (long long)(n0 + lm) * ldb + k0;

    float acc[4][4];
#pragma unroll
    for (int i = 0; i < 4; i++)
#pragma unroll
        for (int j = 0; j < 4; j++) acc[i][j] = 0.0f;

    for (int kk = 0; kk < kchunk; kk += 16) {
        float4 av = *(const float4*)(Arow + kk + lk);
        float4 bv = *(const float4*)(Brow + kk + lk);
        __syncthreads();
        As[lk + 0][lm] = av.x; As[lk + 1][lm] = av.y;
        As[lk + 2][lm] = av.z; As[lk + 3][lm] = av.w;
        Bs[lk + 0][lm] = bv.x; Bs[lk + 1][lm] = bv.y;
        Bs[lk + 2][lm] = bv.z; Bs[lk + 3][lm] = bv.w;
        __syncthreads();
#pragma unroll
        for (int k = 0; k < 16; k++) {
            float4 a4 = *(const float4*)&As[k][ty * 4];
            float4 b4 = *(const float4*)&Bs[k][tx * 4];
            float aa[4] = {a4.x, a4.y, a4.z, a4.w};
            float bb[4] = {b4.x, b4.y, b4.z, b4.w};
#pragma unroll
            for (int i = 0; i < 4; i++)
#pragma unroll
                for (int j = 0; j < 4; j++) acc[i][j] = fmaf(aa[i], bb[j], acc[i][j]);
        }
    }

#pragma unroll
    for (int i = 0; i < 4; i++) {
        int r = m0 + ty * 4 + i;
        if (r >= Mv) continue;
        int cr = crow ? crow[r] : r;
        float* Cp = C + (long long)cr * ldc + n0 + tx * 4;
#pragma unroll
        for (int j = 0; j < 4; j++) {
            float v = acc[i][j];
            if (bias) v += bias[n0 + tx * 4 + j];
            Cp[j] = v;
        }
    }
}

// ---------------- transpose encoder_out [B][C][P] -> enc [B][P][C] ----------
__global__ void transpose_enc(const float* __restrict__ eo, float* __restrict__ enc)
{
    __shared__ float t[32][33];
    int b = blockIdx.z;
    int c0 = blockIdx.x * 32, p0 = blockIdx.y * 32;
    int x = threadIdx.x, y = threadIdx.y;       // 32 x 8
    for (int i = y; i < 32; i += 8)
        t[i][x] = eo[((long long)b * NE + c0 + i) * NP + p0 + x];
    __syncthreads();
    for (int i = y; i < 32; i += 8)
        enc[((long long)b * NP + p0 + i) * NE + c0 + x] = t[x][i];
}

// ---------------- mean over pixels: mean[b][c] = avg_p eo[b][c][p] ----------
__global__ void mean_kernel(const float* __restrict__ eo, float* __restrict__ mean)
{
    int row = blockIdx.x * 8 + threadIdx.y;     // b*512 + c, 32768 rows
    int lane = threadIdx.x;
    const float* src = eo + (long long)row * NP;
    float s = 0.0f;
    for (int p = lane; p < NP; p += 32) s += src[p];
#pragma unroll
    for (int o = 16; o > 0; o >>= 1) s += __shfl_xor_sync(0xffffffffu, s, o);
    if (lane == 0) mean[row] = s * (1.0f / NP);
}

// ---------------- setup: bias sum, emb indices, active-row compaction -------
__global__ void setup_kernel(const int* __restrict__ caps, const int* __restrict__ lens,
                             const float* __restrict__ b_ih, const float* __restrict__ b_hh)
{
    int tid = threadIdx.x;
    for (int j = tid; j < 2048; j += 256) g_bsum[j] = b_ih[j] + b_hh[j];
    for (int i = tid; i < NT * NB; i += 256) {
        int t = i / NB, b = i % NB;
        g_capx[i] = caps[b * NL + t];
    }
    __syncthreads();
    if (tid == 0) {
        int cnt = 0;
        for (int t = 0; t < NT; t++)
            for (int b = 0; b < NB; b++)
                if (t < lens[b] - 1) { g_rowA[cnt] = t * NB + b; g_rowO[cnt] = b * NT + t; cnt++; }
        g_nact[0] = cnt;
        for (int i = cnt; i < 2048; i++) { g_rowA[i] = 0; g_rowO[i] = 0; }
    }
}

// ---------------- build stacked weight [Wdec; Wbeta; Whh] -------------------
__global__ void wcat_kernel(const float* __restrict__ Wd, const float* __restrict__ Wb,
                            const float* __restrict__ Whh)
{
    int i = blockIdx.x * blockDim.x + threadIdx.x;
    int off = i * 4;
    if (off >= 3072 * 512) return;
    int j = off >> 9;
    const float* src = (j < 512) ? (Wd + off)
                     : (j < 1024) ? (Wb + off - 512 * 512)
                                  : (Whh + off - 1024 * 512);
    *(float4*)(g_Wcat + off) = *(const float4*)src;
}

// ---------------- attention: e -> softmax -> gated awe (1 block per batch) --
__global__ void attn_kernel(const float* __restrict__ eo,
                            const float* __restrict__ b_dec_att,
                            const float* __restrict__ w_full,
                            const float* __restrict__ b_full,
                            const float* __restrict__ b_beta)
{
    int b = blockIdx.x, tid = threadIdx.x;  // 256 threads
    __shared__ float att2_s[512], w_s[512], red_s[256], alpha_s[256];

    for (int a = tid; a < 512; a += 256) {
        float v = b_dec_att[a];
#pragma unroll
        for (int ks = 0; ks < KS; ks++) v += g_ybuf[ks * NB * 3072 + b * 3072 + a];
        att2_s[a] = v;
        w_s[a] = w_full[a];
    }
    __syncthreads();

    // e[p] for p = tid
    const float* arow = g_att1 + ((long long)b * NP + tid) * NE;
    float acc = 0.0f;
#pragma unroll 4
    for (int a = 0; a < 512; a += 4) {
        float4 v4 = *(const float4*)(arow + a);
        acc = fmaf(fmaxf(v4.x + att2_s[a + 0], 0.0f), w_s[a + 0], acc);
        acc = fmaf(fmaxf(v4.y + att2_s[a + 1], 0.0f), w_s[a + 1], acc);
        acc = fmaf(fmaxf(v4.z + att2_s[a + 2], 0.0f), w_s[a + 2], acc);
        acc = fmaf(fmaxf(v4.w + att2_s[a + 3], 0.0f), w_s[a + 3], acc);
    }
    acc += b_full[0];

    // softmax over 256
    red_s[tid] = acc; __syncthreads();
    for (int s = 128; s > 0; s >>= 1) {
        if (tid < s) red_s[tid] = fmaxf(red_s[tid], red_s[tid + s]);
        __syncthreads();
    }
    float mx = red_s[0]; __syncthreads();
    float ex = expf(acc - mx);
    red_s[tid] = ex; __syncthreads();
    for (int s = 128; s > 0; s >>= 1) {
        if (tid < s) red_s[tid] += red_s[tid + s];
        __syncthreads();
    }
    alpha_s[tid] = ex / red_s[0];
    __syncthreads();

    // awe[c] = gate(c) * sum_p alpha[p] * eo[b][c][p]
    for (int c = tid; c < 512; c += 256) {
        const float* erow = eo + ((long long)b * NE + c) * NP;
        float s = 0.0f;
#pragma unroll 4
        for (int p = 0; p < NP; p += 4) {
            float4 e4 = *(const float4*)(erow + p);
            s = fmaf(e4.x, alpha_s[p + 0], s);
            s = fmaf(e4.y, alpha_s[p + 1], s);
            s = fmaf(e4.z, alpha_s[p + 2], s);
            s = fmaf(e4.w, alpha_s[p + 3], s);
        }
        float gpre = b_beta[c];
#pragma unroll
        for (int ks = 0; ks < KS; ks++) gpre += g_ybuf[ks * NB * 3072 + b * 3072 + 512 + c];
        g_awe[b * NE + c] = sigf(gpre) * s;
    }
}

// ---------------- LSTM pointwise update -------------------------------------
__global__ void lstm_kernel(const float* __restrict__ xprj_t, float* __restrict__ Hall_t)
{
    int b = blockIdx.x, d = threadIdx.x;  // 512 threads
    const float* xp = xprj_t + b * 2048;
    float gi = xp[d], gf = xp[512 + d], gg = xp[1024 + d], go = xp[1536 + d];
#pragma unroll
    for (int ks = 0; ks < KS; ks++) {
        const float* yb = g_ybuf + ks * NB * 3072 + b * 3072 + 1024;
        gi += yb[d]; gf += yb[512 + d]; gg += yb[1024 + d]; go += yb[1536 + d];
        const float* gb = g_gbuf + ks * NB * 2048 + b * 2048;
        gi += gb[d]; gf += gb[512 + d]; gg += gb[1024 + d]; go += gb[1536 + d];
    }
    float cn = sigf(gf) * g_c[b * NE + d] + sigf(gi) * tanhf(gg);
    float hn = sigf(go) * tanhf(cn);
    g_c[b * NE + d] = cn;
    g_h[b * NE + d] = hn;
    Hall_t[b * NE + d] = hn;
}

// ---------------- host launch -----------------------------------------------
extern "C" void kernel_launch(void* const* d_in, const int* in_sizes, int n_in,
                              void* d_out, int out_size)
{
    const float* eo        = (const float*)d_in[0];
    const int*   caps      = (const int*)  d_in[1];
    const int*   lens      = (const int*)  d_in[2];
    const float* W_enc_att = (const float*)d_in[3];
    const float* b_enc_att = (const float*)d_in[4];
    const float* W_dec_att = (const float*)d_in[5];
    const float* b_dec_att = (const float*)d_in[6];
    const float* w_full    = (const float*)d_in[7];
    const float* b_full    = (const float*)d_in[8];
    const float* emb       = (const float*)d_in[9];
    const float* W_ih      = (const float*)d_in[10];
    const float* W_hh      = (const float*)d_in[11];
    const float* b_ih      = (const float*)d_in[12];
    const float* b_hh      = (const float*)d_in[13];
    const float* W_init_h  = (const float*)d_in[14];
    const float* b_init_h  = (const float*)d_in[15];
    const float* W_init_c  = (const float*)d_in[16];
    const float* b_init_c  = (const float*)d_in[17];
    const float* W_beta    = (const float*)d_in[18];
    const float* b_beta    = (const float*)d_in[19];
    const float* W_fc      = (const float*)d_in[20];
    const float* b_fc      = (const float*)d_in[21];
    float* out = (float*)d_out;

    float *enc, *att1, *mean, *h, *c, *Hall, *xprj, *ybuf, *gbuf, *awe, *Wcat, *bsum;
    int *capx, *rowA, *rowO, *nact;
    cudaGetSymbolAddress((void**)&enc,  g_enc);
    cudaGetSymbolAddress((void**)&att1, g_att1);
    cudaGetSymbolAddress((void**)&mean, g_mean);
    cudaGetSymbolAddress((void**)&h,    g_h);
    cudaGetSymbolAddress((void**)&c,    g_c);
    cudaGetSymbolAddress((void**)&Hall, g_Hall);
    cudaGetSymbolAddress((void**)&xprj, g_xprj);
    cudaGetSymbolAddress((void**)&ybuf, g_ybuf);
    cudaGetSymbolAddress((void**)&gbuf, g_gbuf);
    cudaGetSymbolAddress((void**)&awe,  g_awe);
    cudaGetSymbolAddress((void**)&Wcat, g_Wcat);
    cudaGetSymbolAddress((void**)&bsum, g_bsum);
    cudaGetSymbolAddress((void**)&capx, g_capx);
    cudaGetSymbolAddress((void**)&rowA, g_rowA);
    cudaGetSymbolAddress((void**)&rowO, g_rowO);
    cudaGetSymbolAddress((void**)&nact, g_nact);

    // zero output (masked rows must be exactly 0)
    cudaMemsetAsync(out, 0, (size_t)out_size * sizeof(float));

    transpose_enc<<<dim3(16, 8, 64), dim3(32, 8)>>>(eo, enc);
    mean_kernel<<<4096, dim3(32, 8)>>>(eo, mean);
    setup_kernel<<<1, 256>>>(caps, lens, b_ih, b_hh);
    wcat_kernel<<<1536, 256>>>(W_dec_att, W_beta, W_hh);

    // att1[b,p,:] = enc[b,p,:] @ W_enc_att^T + b_enc_att   (M=16384,N=512,K=512)
    sgemm64<<<dim3(256, 8, 1), 256>>>(enc, 512, nullptr, W_enc_att, 512, b_enc_att,
                                      att1, 512, nullptr, NB * NP, nullptr, 512, 0);
    // h0 / c0 from mean_enc
    sgemm64<<<dim3(1, 8, 1), 256>>>(mean, 512, nullptr, W_init_h, 512, b_init_h,
                                    h, 512, nullptr, NB, nullptr, 512, 0);
    sgemm64<<<dim3(1, 8, 1), 256>>>(mean, 512, nullptr, W_init_c, 512, b_init_c,
                                    c, 512, nullptr, NB, nullptr, 512, 0);
    // x_proj[t,b,:] = emb[cap(t,b)] @ W_ih[:, :256]^T + (b_ih + b_hh)
    sgemm64<<<dim3(31, 32, 1), 256>>>(emb, 256, capx, W_ih, 768, bsum,
                                      xprj, 2048, nullptr, NT * NB, nullptr, 256, 0);

    for (int t = 0; t < NT; t++) {
        // y = h @ [Wdec; Wbeta; Whh]^T  (split-K partials)
        sgemm64<<<dim3(1, 48, KS), 256>>>(h, 512, nullptr, Wcat, 512, nullptr,
                                          ybuf, 3072, nullptr, NB, nullptr,
                                          512 / KS, (long long)NB * 3072);
        attn_kernel<<<NB, 256>>>(eo, b_dec_att, w_full, b_full, b_beta);
        // g = awe @ W_ih[:, 256:768]^T  (split-K partials)
        sgemm64<<<dim3(1, 32, KS), 256>>>(awe, 512, nullptr, W_ih + 256, 768, nullptr,
                                          gbuf, 2048, nullptr, NB, nullptr,
                                          512 / KS, (long long)NB * 2048);
        lstm_kernel<<<NB, 512>>>(xprj + (long long)t * NB * 2048,
                                 Hall + (long long)t * NB * NE);
    }

    // Final FC over compacted active (t,b) rows:
    // out[b,t,:] = Hall[t,b,:] @ W_fc^T + b_fc  (M = n_active on device)
    sgemm64<<<dim3(31, 250, 1), 256>>>(Hall, 512, rowA, W_fc, 512, b_fc,
                                       out, NV, rowO, NT * NB, nact, 512, 0);
}

// round 2
// speedup vs baseline: 1.0472x; 1.0472x over previous
#include <cuda_runtime.h>
#include <math.h>

// Problem constants
#define NB   64     // batch
#define NL   32     // caption length
#define NT   31     // decode steps = L-1
#define NV   16000  // vocab
#define NE   512    // ENC = DEC = ATT
#define NEMB 256
#define NP   256    // pixels
#define KS   4      // split-K factor for small-M step GEMMs

// ---------------- device scratch (no allocation allowed) ----------------
__device__ float g_enc [NB * NP * NE];        // [B][P][C]
__device__ float g_att1[NB * NP * NE];        // [B][P][A]
__device__ float g_mean[NB * NE];
__device__ float g_h   [NB * NE];
__device__ float g_c   [NB * NE];
__device__ float g_Hall[NT * NB * NE];        // h2 per step
__device__ float g_xprj[NT * NB * 2048];      // emb part of gates + b_ih + b_hh
__device__ float g_ybuf[KS * NB * 3072];      // partials of h @ [Wdec; Wbeta; Whh]
__device__ float g_gbuf[KS * NB * 2048];      // partials of awe @ W_ih[:,256:]
__device__ float g_awe [NB * NE];
__device__ float g_Wcat[3072 * 512];          // stacked [Wdec; Wbeta; Whh]
__device__ float g_bsum[2048];                // b_ih + b_hh
__device__ int   g_capx[2048];                // emb row per (t,b)
__device__ int   g_rowA[2048];                // active row -> t*64+b (into Hall)
__device__ int   g_rowO[2048];                // active row -> b*31+t (into out)
__device__ int   g_nact[1];

__device__ __forceinline__ float sigf(float x) { return 1.0f / (1.0f + expf(-x)); }

// ============================================================================
// High-throughput SGEMM: C[M,N] = A[M,K] * B[N,K]^T (+bias)
// 128x128 tile, BK=8, 256 threads, 8x8 per thread (4+4 split), double-buffered.
// A rows optionally gathered via arow[]; C rows optionally scattered via crow[].
// Requires: K % 8 == 0, N tile-aligned (N % 128 == 0), lda/ldb >= K.
// ============================================================================
__global__ void __launch_bounds__(256, 2)
sgemm128(const float* __restrict__ A, int lda, const int* __restrict__ arow,
         const float* __restrict__ B, int ldb,
         const float* __restrict__ bias,
         float* __restrict__ C, int ldc, const int* __restrict__ crow,
         int M, const int* __restrict__ Mdev, int K)
{
    int Mv = Mdev ? *Mdev : M;
    int m0 = blockIdx.x * 128;
    if (m0 >= Mv) return;
    int n0 = blockIdx.y * 128;

    __shared__ float As[2][8][128];
    __shared__ float Bs[2][8][128];

    int tid = threadIdx.x;            // 256 threads
    int lrow = tid >> 1;              // 0..127
    int lk4  = (tid & 1) * 4;         // 0 or 4 (K offset)

    int rowm = m0 + lrow;
    int ca   = (rowm < Mv) ? rowm : (Mv - 1);
    int ar   = arow ? arow[ca] : ca;
    const float* Ap = A + (long long)ar * lda + lk4;
    const float* Bp = B + (long long)(n0 + lrow) * ldb + lk4;

    int tx = tid & 15;                // 0..15 (col quad)
    int ty = tid >> 4;                // 0..15 (row quad)

    float acc[8][8];
#pragma unroll
    for (int i = 0; i < 8; i++)
#pragma unroll
        for (int j = 0; j < 8; j++) acc[i][j] = 0.0f;

    // prologue: load K-tile 0
    {
        float4 a4 = *(const float4*)Ap;
        float4 b4 = *(const float4*)Bp;
        As[0][lk4 + 0][lrow] = a4.x; As[0][lk4 + 1][lrow] = a4.y;
        As[0][lk4 + 2][lrow] = a4.z; As[0][lk4 + 3][lrow] = a4.w;
        Bs[0][lk4 + 0][lrow] = b4.x; Bs[0][lk4 + 1][lrow] = b4.y;
        Bs[0][lk4 + 2][lrow] = b4.z; Bs[0][lk4 + 3][lrow] = b4.w;
    }
    __syncthreads();

    int ntiles = K >> 3;
    int buf = 0;
    for (int t = 0; t < ntiles; t++) {
        float4 na, nb;
        bool more = (t + 1 < ntiles);
        if (more) {
            int kk = (t + 1) << 3;
            na = *(const float4*)(Ap + kk);
            nb = *(const float4*)(Bp + kk);
        }
#pragma unroll
        for (int k = 0; k < 8; k++) {
            float a[8], b[8];
            *(float4*)(a)     = *(const float4*)&As[buf][k][ty * 4];
            *(float4*)(a + 4) = *(const float4*)&As[buf][k][64 + ty * 4];
            *(float4*)(b)     = *(const float4*)&Bs[buf][k][tx * 4];
            *(float4*)(b + 4) = *(const float4*)&Bs[buf][k][64 + tx * 4];
#pragma unroll
            for (int i = 0; i < 8; i++)
#pragma unroll
                for (int j = 0; j < 8; j++)
                    acc[i][j] = fmaf(a[i], b[j], acc[i][j]);
        }
        if (more) {
            int nbuf = buf ^ 1;
            As[nbuf][lk4 + 0][lrow] = na.x; As[nbuf][lk4 + 1][lrow] = na.y;
            As[nbuf][lk4 + 2][lrow] = na.z; As[nbuf][lk4 + 3][lrow] = na.w;
            Bs[nbuf][lk4 + 0][lrow] = nb.x; Bs[nbuf][lk4 + 1][lrow] = nb.y;
            Bs[nbuf][lk4 + 2][lrow] = nb.z; Bs[nbuf][lk4 + 3][lrow] = nb.w;
            __syncthreads();
            buf = nbuf;
        }
    }

    // epilogue: bias + store (rows split 4+4, cols split 4+4)
    float bv[8];
#pragma unroll
    for (int jh = 0; jh < 2; jh++)
#pragma unroll
        for (int j = 0; j < 4; j++)
            bv[jh * 4 + j] = bias ? bias[n0 + jh * 64 + tx * 4 + j] : 0.0f;

#pragma unroll
    for (int i = 0; i < 8; i++) {
        int r = m0 + ((i < 4) ? (ty * 4 + i) : (64 + ty * 4 + i - 4));
        if (r >= Mv) continue;
        int cr = crow ? crow[r] : r;
        float* Cp = C + (long long)cr * ldc + n0;
#pragma unroll
        for (int jh = 0; jh < 2; jh++) {
            float4 v;
            v.x = acc[i][jh * 4 + 0] + bv[jh * 4 + 0];
            v.y = acc[i][jh * 4 + 1] + bv[jh * 4 + 1];
            v.z = acc[i][jh * 4 + 2] + bv[jh * 4 + 2];
            v.w = acc[i][jh * 4 + 3] + bv[jh * 4 + 3];
            *(float4*)(Cp + jh * 64 + tx * 4) = v;
        }
    }
}

// ---------------- small tiled SGEMM (latency-bound step GEMMs) --------------
__global__ void sgemm64(const float* __restrict__ A, int lda, const int* __restrict__ arow,
                        const float* __restrict__ B, int ldb,
                        const float* __restrict__ bias,
                        float* __restrict__ C, int ldc, const int* __restrict__ crow,
                        int M, const int* __restrict__ Mdev,
                        int kchunk, long long czstride)
{
    int Mv = Mdev ? *Mdev : M;
    int m0 = blockIdx.x * 64;
    if (m0 >= Mv) return;
    int n0 = blockIdx.y * 64;
    int k0 = blockIdx.z * kchunk;
    C += (long long)blockIdx.z * czstride;

    __shared__ float As[16][68];
    __shared__ float Bs[16][68];

    int tid = threadIdx.x;        // 256 threads
    int tx = tid & 15;            // col group
    int ty = tid >> 4;            // row group
    int lm = tid >> 2;            // 0..63: tile row/col for loading
    int lk = (tid & 3) * 4;       // 0,4,8,12

    int rowm = m0 + lm;
    int ca   = (rowm < Mv) ? rowm : (Mv - 1);
    int ar   = arow ? arow[ca] : ca;
    const float* Arow = A + (long long)ar * lda + k0;
    const float* Brow = B + (long long)(n0 + lm) * ldb + k0;

    float acc[4][4];
#pragma unroll
    for (int i = 0; i < 4; i++)
#pragma unroll
        for (int j = 0; j < 4; j++) acc[i][j] = 0.0f;

    for (int kk = 0; kk < kchunk; kk += 16) {
        float4 av = *(const float4*)(Arow + kk + lk);
        float4 bv = *(const float4*)(Brow + kk + lk);
        __syncthreads();
        As[lk + 0][lm] = av.x; As[lk + 1][lm] = av.y;
        As[lk + 2][lm] = av.z; As[lk + 3][lm] = av.w;
        Bs[lk + 0][lm] = bv.x; Bs[lk + 1][lm] = bv.y;
        Bs[lk + 2][lm] = bv.z; Bs[lk + 3][lm] = bv.w;
        __syncthreads();
#pragma unroll
        for (int k = 0; k < 16; k++) {
            float4 a4 = *(const float4*)&As[k][ty * 4];
            float4 b4 = *(const float4*)&Bs[k][tx * 4];
            float aa[4] = {a4.x, a4.y, a4.z, a4.w};
            float bb[4] = {b4.x, b4.y, b4.z, b4.w};
#pragma unroll
            for (int i = 0; i < 4; i++)
#pragma unroll
                for (int j = 0; j < 4; j++) acc[i][j] = fmaf(aa[i], bb[j], acc[i][j]);
        }
    }

#pragma unroll
    for (int i = 0; i < 4; i++) {
        int r = m0 + ty * 4 + i;
        if (r >= Mv) continue;
        int cr = crow ? crow[r] : r;
        float* Cp = C + (long long)cr * ldc + n0 + tx * 4;
#pragma unroll
        for (int j = 0; j < 4; j++) {
            float v = acc[i][j];
            if (bias) v += bias[n0 + tx * 4 + j];
            Cp[j] = v;
        }
    }
}

// ---------------- transpose encoder_out [B][C][P] -> enc [B][P][C] ----------
__global__ void transpose_enc(const float* __restrict__ eo, float* __restrict__ enc)
{
    __shared__ float t[32][33];
    int b = blockIdx.z;
    int c0 = blockIdx.x * 32, p0 = blockIdx.y * 32;
    int x = threadIdx.x, y = threadIdx.y;       // 32 x 8
    for (int i = y; i < 32; i += 8)
        t[i][x] = eo[((long long)b * NE + c0 + i) * NP + p0 + x];
    __syncthreads();
    for (int i = y; i < 32; i += 8)
        enc[((long long)b * NP + p0 + i) * NE + c0 + x] = t[x][i];
}

// ---------------- mean over pixels: mean[b][c] = avg_p eo[b][c][p] ----------
__global__ void mean_kernel(const float* __restrict__ eo, float* __restrict__ mean)
{
    int row = blockIdx.x * 8 + threadIdx.y;     // b*512 + c, 32768 rows
    int lane = threadIdx.x;
    const float* src = eo + (long long)row * NP;
    float s = 0.0f;
    for (int p = lane; p < NP; p += 32) s += src[p];
#pragma unroll
    for (int o = 16; o > 0; o >>= 1) s += __shfl_xor_sync(0xffffffffu, s, o);
    if (lane == 0) mean[row] = s * (1.0f / NP);
}

// ---------------- setup: bias sum, emb indices, active-row compaction -------
__global__ void setup_kernel(const int* __restrict__ caps, const int* __restrict__ lens,
                             const float* __restrict__ b_ih, const float* __restrict__ b_hh)
{
    int tid = threadIdx.x;
    for (int j = tid; j < 2048; j += 256) g_bsum[j] = b_ih[j] + b_hh[j];
    for (int i = tid; i < NT * NB; i += 256) {
        int t = i / NB, b = i % NB;
        g_capx[i] = caps[b * NL + t];
    }
    __syncthreads();
    if (tid == 0) {
        int cnt = 0;
        for (int t = 0; t < NT; t++)
            for (int b = 0; b < NB; b++)
                if (t < lens[b] - 1) { g_rowA[cnt] = t * NB + b; g_rowO[cnt] = b * NT + t; cnt++; }
        g_nact[0] = cnt;
        for (int i = cnt; i < 2048; i++) { g_rowA[i] = 0; g_rowO[i] = 0; }
    }
}

// ---------------- build stacked weight [Wdec; Wbeta; Whh] -------------------
__global__ void wcat_kernel(const float* __restrict__ Wd, const float* __restrict__ Wb,
                            const float* __restrict__ Whh)
{
    int i = blockIdx.x * blockDim.x + threadIdx.x;
    int off = i * 4;
    if (off >= 3072 * 512) return;
    int j = off >> 9;
    const float* src = (j < 512) ? (Wd + off)
                     : (j < 1024) ? (Wb + off - 512 * 512)
                                  : (Whh + off - 1024 * 512);
    *(float4*)(g_Wcat + off) = *(const float4*)src;
}

// ---------------- attention: e -> softmax -> gated awe (1 block per batch) --
__global__ void attn_kernel(const float* __restrict__ eo,
                            const float* __restrict__ b_dec_att,
                            const float* __restrict__ w_full,
                            const float* __restrict__ b_full,
                            const float* __restrict__ b_beta)
{
    int b = blockIdx.x, tid = threadIdx.x;  // 256 threads
    __shared__ float att2_s[512], w_s[512], red_s[256], alpha_s[256];

    for (int a = tid; a < 512; a += 256) {
        float v = b_dec_att[a];
#pragma unroll
        for (int ks = 0; ks < KS; ks++) v += g_ybuf[ks * NB * 3072 + b * 3072 + a];
        att2_s[a] = v;
        w_s[a] = w_full[a];
    }
    __syncthreads();

    // e[p] for p = tid
    const float* arow = g_att1 + ((long long)b * NP + tid) * NE;
    float acc = 0.0f;
#pragma unroll 4
    for (int a = 0; a < 512; a += 4) {
        float4 v4 = *(const float4*)(arow + a);
        acc = fmaf(fmaxf(v4.x + att2_s[a + 0], 0.0f), w_s[a + 0], acc);
        acc = fmaf(fmaxf(v4.y + att2_s[a + 1], 0.0f), w_s[a + 1], acc);
        acc = fmaf(fmaxf(v4.z + att2_s[a + 2], 0.0f), w_s[a + 2], acc);
        acc = fmaf(fmaxf(v4.w + att2_s[a + 3], 0.0f), w_s[a + 3], acc);
    }
    acc += b_full[0];

    // softmax over 256
    red_s[tid] = acc; __syncthreads();
    for (int s = 128; s > 0; s >>= 1) {
        if (tid < s) red_s[tid] = fmaxf(red_s[tid], red_s[tid + s]);
        __syncthreads();
    }
    float mx = red_s[0]; __syncthreads();
    float ex = expf(acc - mx);
    red_s[tid] = ex; __syncthreads();
    for (int s = 128; s > 0; s >>= 1) {
        if (tid < s) red_s[tid] += red_s[tid + s];
        __syncthreads();
    }
    alpha_s[tid] = ex / red_s[0];
    __syncthreads();

    // awe[c] = gate(c) * sum_p alpha[p] * eo[b][c][p]
    for (int c = tid; c < 512; c += 256) {
        const float* erow = eo + ((long long)b * NE + c) * NP;
        float s = 0.0f;
#pragma unroll 4
        for (int p = 0; p < NP; p += 4) {
            float4 e4 = *(const float4*)(erow + p);
            s = fmaf(e4.x, alpha_s[p + 0], s);
            s = fmaf(e4.y, alpha_s[p + 1], s);
            s = fmaf(e4.z, alpha_s[p + 2], s);
            s = fmaf(e4.w, alpha_s[p + 3], s);
        }
        float gpre = b_beta[c];
#pragma unroll
        for (int ks = 0; ks < KS; ks++) gpre += g_ybuf[ks * NB * 3072 + b * 3072 + 512 + c];
        g_awe[b * NE + c] = sigf(gpre) * s;
    }
}

// ---------------- LSTM pointwise update -------------------------------------
__global__ void lstm_kernel(const float* __restrict__ xprj_t, float* __restrict__ Hall_t)
{
    int b = blockIdx.x, d = threadIdx.x;  // 512 threads
    const float* xp = xprj_t + b * 2048;
    float gi = xp[d], gf = xp[512 + d], gg = xp[1024 + d], go = xp[1536 + d];
#pragma unroll
    for (int ks = 0; ks < KS; ks++) {
        const float* yb = g_ybuf + ks * NB * 3072 + b * 3072 + 1024;
        gi += yb[d]; gf += yb[512 + d]; gg += yb[1024 + d]; go += yb[1536 + d];
        const float* gb = g_gbuf + ks * NB * 2048 + b * 2048;
        gi += gb[d]; gf += gb[512 + d]; gg += gb[1024 + d]; go += gb[1536 + d];
    }
    float cn = sigf(gf) * g_c[b * NE + d] + sigf(gi) * tanhf(gg);
    float hn = sigf(go) * tanhf(cn);
    g_c[b * NE + d] = cn;
    g_h[b * NE + d] = hn;
    Hall_t[b * NE + d] = hn;
}

// ---------------- host launch -----------------------------------------------
extern "C" void kernel_launch(void* const* d_in, const int* in_sizes, int n_in,
                              void* d_out, int out_size)
{
    const float* eo        = (const float*)d_in[0];
    const int*   caps      = (const int*)  d_in[1];
    const int*   lens      = (const int*)  d_in[2];
    const float* W_enc_att = (const float*)d_in[3];
    const float* b_enc_att = (const float*)d_in[4];
    const float* W_dec_att = (const float*)d_in[5];
    const float* b_dec_att = (const float*)d_in[6];
    const float* w_full    = (const float*)d_in[7];
    const float* b_full    = (const float*)d_in[8];
    const float* emb       = (const float*)d_in[9];
    const float* W_ih      = (const float*)d_in[10];
    const float* W_hh      = (const float*)d_in[11];
    const float* b_ih      = (const float*)d_in[12];
    const float* b_hh      = (const float*)d_in[13];
    const float* W_init_h  = (const float*)d_in[14];
    const float* b_init_h  = (const float*)d_in[15];
    const float* W_init_c  = (const float*)d_in[16];
    const float* b_init_c  = (const float*)d_in[17];
    const float* W_beta    = (const float*)d_in[18];
    const float* b_beta    = (const float*)d_in[19];
    const float* W_fc      = (const float*)d_in[20];
    const float* b_fc      = (const float*)d_in[21];
    float* out = (float*)d_out;

    float *enc, *att1, *mean, *h, *c, *Hall, *xprj, *ybuf, *gbuf, *awe, *Wcat, *bsum;
    int *capx, *rowA, *rowO, *nact;
    cudaGetSymbolAddress((void**)&enc,  g_enc);
    cudaGetSymbolAddress((void**)&att1, g_att1);
    cudaGetSymbolAddress((void**)&mean, g_mean);
    cudaGetSymbolAddress((void**)&h,    g_h);
    cudaGetSymbolAddress((void**)&c,    g_c);
    cudaGetSymbolAddress((void**)&Hall, g_Hall);
    cudaGetSymbolAddress((void**)&xprj, g_xprj);
    cudaGetSymbolAddress((void**)&ybuf, g_ybuf);
    cudaGetSymbolAddress((void**)&gbuf, g_gbuf);
    cudaGetSymbolAddress((void**)&awe,  g_awe);
    cudaGetSymbolAddress((void**)&Wcat, g_Wcat);
    cudaGetSymbolAddress((void**)&bsum, g_bsum);
    cudaGetSymbolAddress((void**)&capx, g_capx);
    cudaGetSymbolAddress((void**)&rowA, g_rowA);
    cudaGetSymbolAddress((void**)&rowO, g_rowO);
    cudaGetSymbolAddress((void**)&nact, g_nact);

    // zero output (masked rows must be exactly 0)
    cudaMemsetAsync(out, 0, (size_t)out_size * sizeof(float));

    transpose_enc<<<dim3(16, 8, 64), dim3(32, 8)>>>(eo, enc);
    mean_kernel<<<4096, dim3(32, 8)>>>(eo, mean);
    setup_kernel<<<1, 256>>>(caps, lens, b_ih, b_hh);
    wcat_kernel<<<1536, 256>>>(W_dec_att, W_beta, W_hh);

    // att1[b,p,:] = enc[b,p,:] @ W_enc_att^T + b_enc_att   (M=16384,N=512,K=512)
    sgemm128<<<dim3(128, 4), 256>>>(enc, 512, nullptr, W_enc_att, 512, b_enc_att,
                                    att1, 512, nullptr, NB * NP, nullptr, 512);
    // h0 / c0 from mean_enc
    sgemm64<<<dim3(1, 8, 1), 256>>>(mean, 512, nullptr, W_init_h, 512, b_init_h,
                                    h, 512, nullptr, NB, nullptr, 512, 0);
    sgemm64<<<dim3(1, 8, 1), 256>>>(mean, 512, nullptr, W_init_c, 512, b_init_c,
                                    c, 512, nullptr, NB, nullptr, 512, 0);
    // x_proj[t,b,:] = emb[cap(t,b)] @ W_ih[:, :256]^T + (b_ih + b_hh)
    sgemm128<<<dim3(16, 16), 256>>>(emb, 256, capx, W_ih, 768, bsum,
                                    xprj, 2048, nullptr, NT * NB, nullptr, 256);

    for (int t = 0; t < NT; t++) {
        // y = h @ [Wdec; Wbeta; Whh]^T  (split-K partials)
        sgemm64<<<dim3(1, 48, KS), 256>>>(h, 512, nullptr, Wcat, 512, nullptr,
                                          ybuf, 3072, nullptr, NB, nullptr,
                                          512 / KS, (long long)NB * 3072);
        attn_kernel<<<NB, 256>>>(eo, b_dec_att, w_full, b_full, b_beta);
        // g = awe @ W_ih[:, 256:768]^T  (split-K partials)
        sgemm64<<<dim3(1, 32, KS), 256>>>(awe, 512, nullptr, W_ih + 256, 768, nullptr,
                                          gbuf, 2048, nullptr, NB, nullptr,
                                          512 / KS, (long long)NB * 2048);
        lstm_kernel<<<NB, 512>>>(xprj + (long long)t * NB * 2048,
                                 Hall + (long long)t * NB * NE);
    }

    // Final FC over compacted active (t,b) rows:
    // out[b,t,:] = Hall[t,b,:] @ W_fc^T + b_fc  (M = n_active on device)
    sgemm128<<<dim3(16, 125), 256>>>(Hall, 512, rowA, W_fc, 512, b_fc,
                                     out, NV, rowO, NT * NB, nact, 512);
}